// round 13
// baseline (speedup 1.0000x reference)
#include <cuda_runtime.h>
#include <cuda_bf16.h>
#include <math.h>
#include <stdint.h>

#define NS 19200   // T*H*W
#define TT 12
#define HH 40
#define WW 40
#define CC 128

// Scratch (device globals)
__device__ float    g_inv[NS];           // per-position inv-norm * sqrt(C)
__device__ uint32_t g_q[NS * 64];        // q rows, bf16x2, pre-scaled by C^-0.5
__device__ uint32_t g_k[NS * 64];        // k rows, bf16x2
__device__ uint32_t g_v[NS * 64];        // v rows, bf16x2
__device__ uint32_t g_att[NS * 64];      // attention output rows, bf16x2
__device__ uint32_t g_wqkv[384 * 64];    // qkv_w bf16x2
__device__ uint32_t g_wproj[128 * 64];   // proj_w bf16x2

__device__ __forceinline__ void mma_bf16(float* c, const uint32_t* a, const uint32_t* b) {
    asm volatile(
        "mma.sync.aligned.m16n8k16.row.col.f32.bf16.bf16.f32 "
        "{%0,%1,%2,%3}, {%4,%5,%6,%7}, {%8,%9}, {%0,%1,%2,%3};\n"
        : "+f"(c[0]), "+f"(c[1]), "+f"(c[2]), "+f"(c[3])
        : "r"(a[0]), "r"(a[1]), "r"(a[2]), "r"(a[3]), "r"(b[0]), "r"(b[1]));
}

__device__ __forceinline__ uint32_t pack_bf16(float x, float y) {
    uint32_t r;
    asm("cvt.rn.bf16x2.f32 %0, %1, %2;" : "=r"(r) : "f"(y), "f"(x));  // lo=x, hi=y
    return r;
}

// ---------------------------------------------------------------------------
// Kernel 0: weight prep, fp32 -> bf16x2
// ---------------------------------------------------------------------------
__global__ void prep_w(const float* __restrict__ qkv_w, const float* __restrict__ proj_w) {
    int i = blockIdx.x * blockDim.x + threadIdx.x;   // 0 .. 32767
    if (i < 384 * 64) {
        float2 v = *(const float2*)(qkv_w + i * 2);
        g_wqkv[i] = pack_bf16(v.x, v.y);
    } else {
        int j = i - 384 * 64;
        float2 v = *(const float2*)(proj_w + j * 2);
        g_wproj[j] = pack_bf16(v.x, v.y);
    }
}

// ---------------------------------------------------------------------------
// Kernel 1: per-position inv norm
// ---------------------------------------------------------------------------
__global__ void inv_kernel(const float* __restrict__ x) {
    int s4 = (blockIdx.x * blockDim.x + threadIdx.x) * 4;
    if (s4 >= NS) return;
    float4 ss = {0.f, 0.f, 0.f, 0.f};
#pragma unroll 8
    for (int c = 0; c < CC; c++) {
        float4 v = *(const float4*)(x + (size_t)c * NS + s4);
        ss.x = fmaf(v.x, v.x, ss.x);
        ss.y = fmaf(v.y, v.y, ss.y);
        ss.z = fmaf(v.z, v.z, ss.z);
        ss.w = fmaf(v.w, v.w, ss.w);
    }
    const float sC = 11.313708498984761f;  // sqrt(128)
    float4 inv;
    inv.x = sC / fmaxf(sqrtf(ss.x), 1e-12f);
    inv.y = sC / fmaxf(sqrtf(ss.y), 1e-12f);
    inv.z = sC / fmaxf(sqrtf(ss.z), 1e-12f);
    inv.w = sC / fmaxf(sqrtf(ss.w), 1e-12f);
    *(float4*)(g_inv + s4) = inv;
}

// ---------------------------------------------------------------------------
// GEMM common bits
// ---------------------------------------------------------------------------
#define LDU 68
#define A_U (64 * LDU)
#define B128_U (128 * LDU)

__device__ __forceinline__ void gemm_core(const uint32_t* As, const uint32_t* Bs,
                                          int wm, int wn, int g, int tg,
                                          float acc[2][4][4]) {
#pragma unroll
    for (int ks = 0; ks < 8; ks++) {
        int kb = ks * 8;
        uint32_t af[2][4], bf[4][2];
#pragma unroll
        for (int mt = 0; mt < 2; mt++) {
            int m = wm * 32 + mt * 16 + g;
            af[mt][0] = As[m * LDU + kb + tg];
            af[mt][1] = As[(m + 8) * LDU + kb + tg];
            af[mt][2] = As[m * LDU + kb + tg + 4];
            af[mt][3] = As[(m + 8) * LDU + kb + tg + 4];
        }
#pragma unroll
        for (int nt = 0; nt < 4; nt++) {
            int n = wn * 32 + nt * 8 + g;
            bf[nt][0] = Bs[n * LDU + kb + tg];
            bf[nt][1] = Bs[n * LDU + kb + tg + 4];
        }
#pragma unroll
        for (int mt = 0; mt < 2; mt++)
#pragma unroll
            for (int nt = 0; nt < 4; nt++)
                mma_bf16(acc[mt][nt], af[mt], bf[nt]);
    }
}

// ---------------------------------------------------------------------------
// Kernel 2: qkv GEMM (round-10/11/12 winner, unchanged)
// ---------------------------------------------------------------------------
#define QKV_SMEM ((A_U + B128_U) * 4)   // 52224 B
static_assert(QKV_SMEM <= 227 * 1024, "qkv smem");

__global__ void __launch_bounds__(256, 2)
gemm_qkv(const float* __restrict__ x, const float* __restrict__ gamma,
         const float* __restrict__ bias) {
    extern __shared__ uint32_t su[];
    uint32_t* As = su;
    uint32_t* Bs = su + A_U;

    int tid = threadIdx.x;
    int lane = tid & 31;
    int warp = tid >> 5;
    int wm = warp & 1, wn = warp >> 1;
    int g = lane >> 2, tg = lane & 3;
    int bx = blockIdx.x, by = blockIdx.y;

#pragma unroll
    for (int i = 0; i < 8; i++) {
        int id = tid + i * 256;
        int r = id >> 5, c4 = (id & 31) << 2;
        int row = by * 64 + r;
        int ch = row / 150;
        int s = (row - ch * 150) * 128 + c4;
        float gm = __ldg(&gamma[ch]);
        float4 iv = *(const float4*)(g_inv + s);
        float4 v = *(const float4*)(x + (size_t)row * 128 + c4);
        v.x *= iv.x * gm; v.y *= iv.y * gm; v.z *= iv.z * gm; v.w *= iv.w * gm;
        As[r * LDU + (c4 >> 1)]     = pack_bf16(v.x, v.y);
        As[r * LDU + (c4 >> 1) + 1] = pack_bf16(v.z, v.w);
    }
    const uint32_t* Bbase = g_wqkv + (size_t)bx * 128 * 64;
#pragma unroll
    for (int i = 0; i < 8; i++) {
        int id = tid + i * 256;
        int r = id >> 4, c = (id & 15) * 4;
        uint4 v = *(const uint4*)(Bbase + r * 64 + c);
        *(uint4*)(Bs + r * LDU + c) = v;
    }
    __syncthreads();

    float acc[2][4][4];
#pragma unroll
    for (int i = 0; i < 2; i++)
#pragma unroll
        for (int j = 0; j < 4; j++)
#pragma unroll
            for (int e = 0; e < 4; e++) acc[i][j][e] = 0.f;

    gemm_core(As, Bs, wm, wn, g, tg, acc);

    const float QS = 0.08838834764831845f;
    uint32_t* dst = (bx == 0) ? g_q : (bx == 1) ? g_k : g_v;
    float sc = (bx == 0) ? QS : 1.0f;
#pragma unroll
    for (int nt = 0; nt < 4; nt++) {
        int nloc = wn * 32 + nt * 8 + 2 * tg;
        float2 bb = *(const float2*)(bias + bx * 128 + nloc);
#pragma unroll
        for (int mt = 0; mt < 2; mt++) {
            int row0 = by * 64 + wm * 32 + mt * 16 + g;
            dst[row0 * 64 + (nloc >> 1)] =
                pack_bf16((acc[mt][nt][0] + bb.x) * sc, (acc[mt][nt][1] + bb.y) * sc);
            dst[(row0 + 8) * 64 + (nloc >> 1)] =
                pack_bf16((acc[mt][nt][2] + bb.x) * sc, (acc[mt][nt][3] + bb.y) * sc);
        }
    }
}

// ---------------------------------------------------------------------------
// Kernel 4: proj GEMM (round-10/11/12 winner, unchanged)
// ---------------------------------------------------------------------------
#define PROJ_SMEM (2 * A_U * 4)   // 34816 B
static_assert(PROJ_SMEM <= 227 * 1024, "proj smem");

__global__ void __launch_bounds__(128, 5)
gemm_proj(const float* __restrict__ bias,
          const float* __restrict__ resid, float* __restrict__ outArg) {
    extern __shared__ uint32_t su[];
    uint32_t* As = su;
    uint32_t* Bs = su + A_U;

    int tid = threadIdx.x;
    int lane = tid & 31;
    int warp = tid >> 5;
    int wm = warp & 1, wn = warp >> 1;
    int g = lane >> 2, tg = lane & 3;

    const uint32_t* Abase = g_att + (size_t)blockIdx.y * 64 * 64;
#pragma unroll
    for (int i = 0; i < 8; i++) {
        int id = tid + i * 128;
        int r = id >> 4, c = (id & 15) * 4;
        uint4 v = *(const uint4*)(Abase + r * 64 + c);
        *(uint4*)(As + r * LDU + c) = v;
    }
    const uint32_t* Bbase = g_wproj + (size_t)blockIdx.x * 64 * 64;
#pragma unroll
    for (int i = 0; i < 8; i++) {
        int id = tid + i * 128;
        int r = id >> 4, c = (id & 15) * 4;
        uint4 v = *(const uint4*)(Bbase + r * 64 + c);
        *(uint4*)(Bs + r * LDU + c) = v;
    }
    __syncthreads();

    float acc[2][4][4];
#pragma unroll
    for (int i = 0; i < 2; i++)
#pragma unroll
        for (int j = 0; j < 4; j++)
#pragma unroll
            for (int e = 0; e < 4; e++) acc[i][j][e] = 0.f;

    gemm_core(As, Bs, wm, wn, g, tg, acc);

#pragma unroll
    for (int nt = 0; nt < 4; nt++) {
        int n = blockIdx.x * 64 + wn * 32 + nt * 8 + 2 * tg;
        float2 bb = *(const float2*)(bias + n);
#pragma unroll
        for (int mt = 0; mt < 2; mt++) {
            int row0 = blockIdx.y * 64 + wm * 32 + mt * 16 + g;
            float2 r0 = *(const float2*)(resid + (size_t)row0 * 128 + n);
            float2 r1 = *(const float2*)(resid + (size_t)(row0 + 8) * 128 + n);
            float2 o0 = { acc[mt][nt][0] + bb.x + r0.x, acc[mt][nt][1] + bb.y + r0.y };
            float2 o1 = { acc[mt][nt][2] + bb.x + r1.x, acc[mt][nt][3] + bb.y + r1.y };
            *(float2*)(outArg + (size_t)row0 * 128 + n) = o0;
            *(float2*)(outArg + (size_t)(row0 + 8) * 128 + n) = o1;
        }
    }
}

// ---------------------------------------------------------------------------
// Kernel 3: neighborhood attention, 16 positions/CTA (2t x 2h x 4w).
// ONE shared 96-row buffer reused: K during scores, V during AV.
// smem ~43.6 KB -> 5 CTAs/SM. Phases:
//   0: np/sl/sc tables + q copy         -> sync
//   1: stage K                          -> sync
//   2: score mma (12 n-tiles)           -> sync
//   3: softmax (same-warp aw) + stage V -> sync
//   4: AV scalar
// ---------------------------------------------------------------------------
#define SCW 104    // scall row stride (floats)

__global__ void __launch_bounds__(256)
attn_kernel(const float* __restrict__ rpb) {
    extern __shared__ uint32_t smu[];
    uint32_t* qsm   = smu;                        // [16][LDU]
    uint32_t* kvsm  = qsm + 16 * LDU;             // [96][LDU]  K then V
    float*    scall = (float*)(kvsm + 96 * LDU);  // [16][SCW]
    float*    sc    = scall + 16 * SCW;           // [16][32] bias
    float*    aw    = sc + 512;                   // [16][32] weights
    int*      sl    = (int*)(aw + 512);           // [16][32] slots
    int*      np    = sl + 512;                   // [96] neighbor flat positions

    int tid = threadIdx.x, lane = tid & 31, warp = tid >> 5;
    int g = lane >> 2, tg = lane & 3;
    int w0 = blockIdx.x * 4, h0 = blockIdx.y * 2, t0 = blockIdx.z * 2;

    int tlo = min(max(t0 - 1, 0), TT - 3);
    int hlo = min(max(h0 - 1, 0), HH - 3);
    int wlo = min(max(w0 - 1, 0), WW - 3);

    // phase 0: np table, sl/sc tables, q copy
    if (tid < 96) {
        int dt = tid / 24, rrem = tid % 24;
        int dh = rrem / 6, dw = rrem % 6;
        int nt = min(tlo + dt, TT - 1);
        int nh = min(hlo + dh, HH - 1);
        int nw = min(wlo + dw, WW - 1);
        np[tid] = (nt * HH + nh) * WW + nw;
    }
#pragma unroll
    for (int i = 0; i < 2; i++) {
        int d = tid + i * 256;
        if (d < 432) {
            int j = d / 27, n = d % 27;
            int pt = t0 + (j >> 3), ph = h0 + ((j >> 2) & 1), pw = w0 + (j & 3);
            int dt = n / 9, dh = (n / 3) % 3, dw = n % 3;
            int stt = min(max(pt - 1, 0), TT - 3);
            int sh  = min(max(ph - 1, 0), HH - 3);
            int sw  = min(max(pw - 1, 0), WW - 3);
            int nt = stt + dt, nh = sh + dh, nw = sw + dw;
            sl[j * 32 + n] = ((nt - tlo) * 4 + (nh - hlo)) * 6 + (nw - wlo);
            int bt = nt - pt + 2, bh = nh - ph + 2, bw = nw - pw + 2;
            sc[j * 32 + n] = __ldg(&rpb[(bt * 5 + bh) * 5 + bw]);
        }
    }
#pragma unroll
    for (int i = 0; i < 2; i++) {
        int j = warp + i * 8;
        int pt = t0 + (j >> 3), ph = h0 + ((j >> 2) & 1), pw = w0 + (j & 3);
        int p = (pt * HH + ph) * WW + pw;
        *(uint2*)(qsm + j * LDU + lane * 2) = *(const uint2*)(g_q + p * 64 + lane * 2);
    }
    __syncthreads();

    // phase 1: stage K
    for (int rowid = warp; rowid < 96; rowid += 8)
        *(uint2*)(kvsm + rowid * LDU + lane * 2) =
            *(const uint2*)(g_k + np[rowid] * 64 + lane * 2);
    __syncthreads();

    // phase 2: score mma: 12 n-tiles; warp w does tile w, warps 0-3 also 8+w
    {
        uint32_t af[8][4];
#pragma unroll
        for (int ks = 0; ks < 8; ks++) {
            int kb = ks * 8;
            af[ks][0] = qsm[g * LDU + kb + tg];
            af[ks][1] = qsm[(g + 8) * LDU + kb + tg];
            af[ks][2] = qsm[g * LDU + kb + tg + 4];
            af[ks][3] = qsm[(g + 8) * LDU + kb + tg + 4];
        }
#pragma unroll
        for (int it = 0; it < 2; it++) {
            if (it == 1 && warp >= 4) break;
            int tt = (it == 0) ? warp : warp + 8;
            float a4[4] = {0.f, 0.f, 0.f, 0.f};
            int n = tt * 8 + g;
#pragma unroll
            for (int ks = 0; ks < 8; ks++) {
                int kb = ks * 8;
                uint32_t bf[2];
                bf[0] = kvsm[n * LDU + kb + tg];
                bf[1] = kvsm[n * LDU + kb + tg + 4];
                mma_bf16(a4, af[ks], bf);
            }
            *(float2*)(scall + g * SCW + tt * 8 + 2 * tg) = make_float2(a4[0], a4[1]);
            *(float2*)(scall + (g + 8) * SCW + tt * 8 + 2 * tg) = make_float2(a4[2], a4[3]);
        }
    }
    __syncthreads();

    // phase 3: softmax (writes aw, same-warp consumer) + stage V over K
#pragma unroll
    for (int i = 0; i < 2; i++) {
        int j = warp + i * 8;
        float s = -1e30f;
        if (lane < 27)
            s = sc[j * 32 + lane] + scall[j * SCW + sl[j * 32 + lane]];
        float m = s;
#pragma unroll
        for (int o = 16; o; o >>= 1) m = fmaxf(m, __shfl_xor_sync(0xffffffffu, m, o));
        float e = (lane < 27) ? __expf(s - m) : 0.f;
        float den = e;
#pragma unroll
        for (int o = 16; o; o >>= 1) den += __shfl_xor_sync(0xffffffffu, den, o);
        aw[j * 32 + lane] = e / den;
    }
    for (int rowid = warp; rowid < 96; rowid += 8)
        *(uint2*)(kvsm + rowid * LDU + lane * 2) =
            *(const uint2*)(g_v + np[rowid] * 64 + lane * 2);
    __syncthreads();

    // phase 4: AV
#pragma unroll
    for (int i = 0; i < 2; i++) {
        int j = warp + i * 8;
        int pt = t0 + (j >> 3), ph = h0 + ((j >> 2) & 1), pw = w0 + (j & 3);
        int p = (pt * HH + ph) * WW + pw;
        float4 acc = {0.f, 0.f, 0.f, 0.f};
#pragma unroll
        for (int n = 0; n < 27; n++) {
            float a = aw[j * 32 + n];
            int slot = sl[j * 32 + n];
            uint2 vv = *(const uint2*)(kvsm + slot * LDU + lane * 2);
            float2 f0 = __bfloat1622float2(*(const __nv_bfloat162*)&vv.x);
            float2 f1 = __bfloat1622float2(*(const __nv_bfloat162*)&vv.y);
            acc.x = fmaf(a, f0.x, acc.x);
            acc.y = fmaf(a, f0.y, acc.y);
            acc.z = fmaf(a, f1.x, acc.z);
            acc.w = fmaf(a, f1.y, acc.w);
        }
        uint2 o = { pack_bf16(acc.x, acc.y), pack_bf16(acc.z, acc.w) };
        *(uint2*)(g_att + p * 64 + lane * 2) = o;
    }
}

static const int ATTN_SMEM =
    (16 * LDU + 96 * LDU + 16 * SCW + 512 * 3 + 96) * 4;   // 43648 B
static_assert((16 * LDU + 96 * LDU + 16 * SCW + 512 * 3 + 96) * 4 <= 227 * 1024,
              "attn smem");

// ---------------------------------------------------------------------------
extern "C" void kernel_launch(void* const* d_in, const int* in_sizes, int n_in,
                              void* d_out, int out_size) {
    const float* x      = (const float*)d_in[0];
    const float* gamma  = (const float*)d_in[1];
    const float* qkv_w  = (const float*)d_in[2];
    const float* qkv_b  = (const float*)d_in[3];
    const float* rpb    = (const float*)d_in[4];
    const float* proj_w = (const float*)d_in[5];
    const float* proj_b = (const float*)d_in[6];
    float* out = (float*)d_out;

    cudaFuncSetAttribute(attn_kernel, cudaFuncAttributeMaxDynamicSharedMemorySize, ATTN_SMEM);
    cudaFuncSetAttribute(gemm_qkv,  cudaFuncAttributeMaxDynamicSharedMemorySize, QKV_SMEM);
    cudaFuncSetAttribute(gemm_proj, cudaFuncAttributeMaxDynamicSharedMemorySize, PROJ_SMEM);

    prep_w<<<128, 256>>>(qkv_w, proj_w);
    inv_kernel<<<(NS / 4 + 255) / 256, 256>>>(x);
    gemm_qkv<<<dim3(3, NS / 64), 256, QKV_SMEM>>>(x, gamma, qkv_b);
    attn_kernel<<<dim3(WW / 4, HH / 2, TT / 2), 256, ATTN_SMEM>>>(rpb);
    gemm_proj<<<dim3(2, NS / 64), 128, PROJ_SMEM>>>(proj_b, x, out);
}

// round 14
// speedup vs baseline: 1.1344x; 1.1344x over previous
#include <cuda_runtime.h>
#include <cuda_bf16.h>
#include <math.h>
#include <stdint.h>

#define NS 19200   // T*H*W
#define TT 12
#define HH 40
#define WW 40
#define CC 128

// Scratch (device globals)
__device__ float    g_inv[NS];           // per-position inv-norm * sqrt(C)
__device__ uint32_t g_q[NS * 64];        // q rows, bf16x2, pre-scaled by C^-0.5
__device__ uint32_t g_k[NS * 64];        // k rows, bf16x2
__device__ uint32_t g_v[NS * 64];        // v rows, bf16x2
__device__ uint32_t g_att[NS * 64];      // attention output rows, bf16x2
__device__ uint32_t g_wqkv[384 * 64];    // qkv_w bf16x2
__device__ uint32_t g_wproj[128 * 64];   // proj_w bf16x2

__device__ __forceinline__ void mma_bf16(float* c, const uint32_t* a, const uint32_t* b) {
    asm volatile(
        "mma.sync.aligned.m16n8k16.row.col.f32.bf16.bf16.f32 "
        "{%0,%1,%2,%3}, {%4,%5,%6,%7}, {%8,%9}, {%0,%1,%2,%3};\n"
        : "+f"(c[0]), "+f"(c[1]), "+f"(c[2]), "+f"(c[3])
        : "r"(a[0]), "r"(a[1]), "r"(a[2]), "r"(a[3]), "r"(b[0]), "r"(b[1]));
}

__device__ __forceinline__ uint32_t pack_bf16(float x, float y) {
    uint32_t r;
    asm("cvt.rn.bf16x2.f32 %0, %1, %2;" : "=r"(r) : "f"(y), "f"(x));  // lo=x, hi=y
    return r;
}

// ---------------------------------------------------------------------------
// Kernel 0: weight prep, fp32 -> bf16x2
// ---------------------------------------------------------------------------
__global__ void prep_w(const float* __restrict__ qkv_w, const float* __restrict__ proj_w) {
    int i = blockIdx.x * blockDim.x + threadIdx.x;   // 0 .. 32767
    if (i < 384 * 64) {
        float2 v = *(const float2*)(qkv_w + i * 2);
        g_wqkv[i] = pack_bf16(v.x, v.y);
    } else {
        int j = i - 384 * 64;
        float2 v = *(const float2*)(proj_w + j * 2);
        g_wproj[j] = pack_bf16(v.x, v.y);
    }
}

// ---------------------------------------------------------------------------
// Kernel 1: per-position inv norm
// ---------------------------------------------------------------------------
__global__ void inv_kernel(const float* __restrict__ x) {
    int s4 = (blockIdx.x * blockDim.x + threadIdx.x) * 4;
    if (s4 >= NS) return;
    float4 ss = {0.f, 0.f, 0.f, 0.f};
#pragma unroll 8
    for (int c = 0; c < CC; c++) {
        float4 v = *(const float4*)(x + (size_t)c * NS + s4);
        ss.x = fmaf(v.x, v.x, ss.x);
        ss.y = fmaf(v.y, v.y, ss.y);
        ss.z = fmaf(v.z, v.z, ss.z);
        ss.w = fmaf(v.w, v.w, ss.w);
    }
    const float sC = 11.313708498984761f;  // sqrt(128)
    float4 inv;
    inv.x = sC / fmaxf(sqrtf(ss.x), 1e-12f);
    inv.y = sC / fmaxf(sqrtf(ss.y), 1e-12f);
    inv.z = sC / fmaxf(sqrtf(ss.z), 1e-12f);
    inv.w = sC / fmaxf(sqrtf(ss.w), 1e-12f);
    *(float4*)(g_inv + s4) = inv;
}

// ---------------------------------------------------------------------------
// GEMM common bits
// ---------------------------------------------------------------------------
#define LDU 68
#define A_U (64 * LDU)
#define B128_U (128 * LDU)

__device__ __forceinline__ void gemm_core(const uint32_t* As, const uint32_t* Bs,
                                          int wm, int wn, int g, int tg,
                                          float acc[2][4][4]) {
#pragma unroll
    for (int ks = 0; ks < 8; ks++) {
        int kb = ks * 8;
        uint32_t af[2][4], bf[4][2];
#pragma unroll
        for (int mt = 0; mt < 2; mt++) {
            int m = wm * 32 + mt * 16 + g;
            af[mt][0] = As[m * LDU + kb + tg];
            af[mt][1] = As[(m + 8) * LDU + kb + tg];
            af[mt][2] = As[m * LDU + kb + tg + 4];
            af[mt][3] = As[(m + 8) * LDU + kb + tg + 4];
        }
#pragma unroll
        for (int nt = 0; nt < 4; nt++) {
            int n = wn * 32 + nt * 8 + g;
            bf[nt][0] = Bs[n * LDU + kb + tg];
            bf[nt][1] = Bs[n * LDU + kb + tg + 4];
        }
#pragma unroll
        for (int mt = 0; mt < 2; mt++)
#pragma unroll
            for (int nt = 0; nt < 4; nt++)
                mma_bf16(acc[mt][nt], af[mt], bf[nt]);
    }
}

// ---------------------------------------------------------------------------
// Kernel 2: qkv GEMM (round-10..12 winner, unchanged)
// ---------------------------------------------------------------------------
#define QKV_SMEM ((A_U + B128_U) * 4)   // 52224 B
static_assert(QKV_SMEM <= 227 * 1024, "qkv smem");

__global__ void __launch_bounds__(256, 2)
gemm_qkv(const float* __restrict__ x, const float* __restrict__ gamma,
         const float* __restrict__ bias) {
    extern __shared__ uint32_t su[];
    uint32_t* As = su;
    uint32_t* Bs = su + A_U;

    int tid = threadIdx.x;
    int lane = tid & 31;
    int warp = tid >> 5;
    int wm = warp & 1, wn = warp >> 1;
    int g = lane >> 2, tg = lane & 3;
    int bx = blockIdx.x, by = blockIdx.y;

#pragma unroll
    for (int i = 0; i < 8; i++) {
        int id = tid + i * 256;
        int r = id >> 5, c4 = (id & 31) << 2;
        int row = by * 64 + r;
        int ch = row / 150;
        int s = (row - ch * 150) * 128 + c4;
        float gm = __ldg(&gamma[ch]);
        float4 iv = *(const float4*)(g_inv + s);
        float4 v = *(const float4*)(x + (size_t)row * 128 + c4);
        v.x *= iv.x * gm; v.y *= iv.y * gm; v.z *= iv.z * gm; v.w *= iv.w * gm;
        As[r * LDU + (c4 >> 1)]     = pack_bf16(v.x, v.y);
        As[r * LDU + (c4 >> 1) + 1] = pack_bf16(v.z, v.w);
    }
    const uint32_t* Bbase = g_wqkv + (size_t)bx * 128 * 64;
#pragma unroll
    for (int i = 0; i < 8; i++) {
        int id = tid + i * 256;
        int r = id >> 4, c = (id & 15) * 4;
        uint4 v = *(const uint4*)(Bbase + r * 64 + c);
        *(uint4*)(Bs + r * LDU + c) = v;
    }
    __syncthreads();

    float acc[2][4][4];
#pragma unroll
    for (int i = 0; i < 2; i++)
#pragma unroll
        for (int j = 0; j < 4; j++)
#pragma unroll
            for (int e = 0; e < 4; e++) acc[i][j][e] = 0.f;

    gemm_core(As, Bs, wm, wn, g, tg, acc);

    const float QS = 0.08838834764831845f;
    uint32_t* dst = (bx == 0) ? g_q : (bx == 1) ? g_k : g_v;
    float sc = (bx == 0) ? QS : 1.0f;
#pragma unroll
    for (int nt = 0; nt < 4; nt++) {
        int nloc = wn * 32 + nt * 8 + 2 * tg;
        float2 bb = *(const float2*)(bias + bx * 128 + nloc);
#pragma unroll
        for (int mt = 0; mt < 2; mt++) {
            int row0 = by * 64 + wm * 32 + mt * 16 + g;
            dst[row0 * 64 + (nloc >> 1)] =
                pack_bf16((acc[mt][nt][0] + bb.x) * sc, (acc[mt][nt][1] + bb.y) * sc);
            dst[(row0 + 8) * 64 + (nloc >> 1)] =
                pack_bf16((acc[mt][nt][2] + bb.x) * sc, (acc[mt][nt][3] + bb.y) * sc);
        }
    }
}

// ---------------------------------------------------------------------------
// Kernel 4: proj GEMM (round-10..12 winner, unchanged)
// ---------------------------------------------------------------------------
#define PROJ_SMEM (2 * A_U * 4)   // 34816 B
static_assert(PROJ_SMEM <= 227 * 1024, "proj smem");

__global__ void __launch_bounds__(128, 5)
gemm_proj(const float* __restrict__ bias,
          const float* __restrict__ resid, float* __restrict__ outArg) {
    extern __shared__ uint32_t su[];
    uint32_t* As = su;
    uint32_t* Bs = su + A_U;

    int tid = threadIdx.x;
    int lane = tid & 31;
    int warp = tid >> 5;
    int wm = warp & 1, wn = warp >> 1;
    int g = lane >> 2, tg = lane & 3;

    const uint32_t* Abase = g_att + (size_t)blockIdx.y * 64 * 64;
#pragma unroll
    for (int i = 0; i < 8; i++) {
        int id = tid + i * 128;
        int r = id >> 4, c = (id & 15) * 4;
        uint4 v = *(const uint4*)(Abase + r * 64 + c);
        *(uint4*)(As + r * LDU + c) = v;
    }
    const uint32_t* Bbase = g_wproj + (size_t)blockIdx.x * 64 * 64;
#pragma unroll
    for (int i = 0; i < 8; i++) {
        int id = tid + i * 128;
        int r = id >> 4, c = (id & 15) * 4;
        uint4 v = *(const uint4*)(Bbase + r * 64 + c);
        *(uint4*)(Bs + r * LDU + c) = v;
    }
    __syncthreads();

    float acc[2][4][4];
#pragma unroll
    for (int i = 0; i < 2; i++)
#pragma unroll
        for (int j = 0; j < 4; j++)
#pragma unroll
            for (int e = 0; e < 4; e++) acc[i][j][e] = 0.f;

    gemm_core(As, Bs, wm, wn, g, tg, acc);

#pragma unroll
    for (int nt = 0; nt < 4; nt++) {
        int n = blockIdx.x * 64 + wn * 32 + nt * 8 + 2 * tg;
        float2 bb = *(const float2*)(bias + n);
#pragma unroll
        for (int mt = 0; mt < 2; mt++) {
            int row0 = blockIdx.y * 64 + wm * 32 + mt * 16 + g;
            float2 r0 = *(const float2*)(resid + (size_t)row0 * 128 + n);
            float2 r1 = *(const float2*)(resid + (size_t)(row0 + 8) * 128 + n);
            float2 o0 = { acc[mt][nt][0] + bb.x + r0.x, acc[mt][nt][1] + bb.y + r0.y };
            float2 o1 = { acc[mt][nt][2] + bb.x + r1.x, acc[mt][nt][3] + bb.y + r1.y };
            *(float2*)(outArg + (size_t)row0 * 128 + n) = o0;
            *(float2*)(outArg + (size_t)(row0 + 8) * 128 + n) = o1;
        }
    }
}

// ---------------------------------------------------------------------------
// Kernel 3: neighborhood attention, 16 positions/CTA, 512 threads (16 warps).
// Separate K/V buffers staged once (round-12 plan); warp j owns position j:
// each phase's per-warp serial work is halved vs the 256-thread version.
// ---------------------------------------------------------------------------
#define VPAD 66    // u32 stride for v rows
#define SCW 104    // scall row stride (floats)

__global__ void __launch_bounds__(512)
attn_kernel(const float* __restrict__ rpb) {
    extern __shared__ uint32_t smu[];
    uint32_t* qsm   = smu;                        // [16][LDU]
    uint32_t* ksm   = qsm + 16 * LDU;             // [96][LDU]
    uint32_t* vsm   = ksm + 96 * LDU;             // [96][VPAD]
    float*    scall = (float*)(vsm + 96 * VPAD);  // [16][SCW]
    float*    sc    = scall + 16 * SCW;           // [16][32] bias
    float*    aw    = sc + 512;                   // [16][32] weights
    int*      sl    = (int*)(aw + 512);           // [16][32] slots
    int*      np    = sl + 512;                   // [96]

    int tid = threadIdx.x, lane = tid & 31, warp = tid >> 5;   // warp 0..15
    int g = lane >> 2, tg = lane & 3;
    int w0 = blockIdx.x * 4, h0 = blockIdx.y * 2, t0 = blockIdx.z * 2;

    int tlo = min(max(t0 - 1, 0), TT - 3);
    int hlo = min(max(h0 - 1, 0), HH - 3);
    int wlo = min(max(w0 - 1, 0), WW - 3);

    // warp j -> position j
    int j = warp;
    int pt = t0 + (j >> 3), ph = h0 + ((j >> 2) & 1), pw = w0 + (j & 3);
    int p  = (pt * HH + ph) * WW + pw;

    // phase 0: np table, sl/sc tables (432 <= 512: single pass), q copy
    if (tid < 96) {
        int dt = tid / 24, rrem = tid % 24;
        int dh = rrem / 6, dw = rrem % 6;
        int nt = min(tlo + dt, TT - 1);
        int nh = min(hlo + dh, HH - 1);
        int nw = min(wlo + dw, WW - 1);
        np[tid] = (nt * HH + nh) * WW + nw;
    }
    if (tid < 432) {
        int jj = tid / 27, n = tid % 27;
        int qt = t0 + (jj >> 3), qh = h0 + ((jj >> 2) & 1), qw = w0 + (jj & 3);
        int dt = n / 9, dh = (n / 3) % 3, dw = n % 3;
        int stt = min(max(qt - 1, 0), TT - 3);
        int sh  = min(max(qh - 1, 0), HH - 3);
        int sw  = min(max(qw - 1, 0), WW - 3);
        int nt = stt + dt, nh = sh + dh, nw = sw + dw;
        sl[jj * 32 + n] = ((nt - tlo) * 4 + (nh - hlo)) * 6 + (nw - wlo);
        int bt = nt - qt + 2, bh = nh - qh + 2, bw = nw - qw + 2;
        sc[jj * 32 + n] = __ldg(&rpb[(bt * 5 + bh) * 5 + bw]);
    }
    *(uint2*)(qsm + j * LDU + lane * 2) = *(const uint2*)(g_q + p * 64 + lane * 2);
    __syncthreads();

    // phase 1: stage union k/v rows (6 per warp)
    for (int rowid = warp; rowid < 96; rowid += 16) {
        int base = np[rowid] * 64 + lane * 2;
        *(uint2*)(ksm + rowid * LDU + lane * 2) = *(const uint2*)(g_k + base);
        *(uint2*)(vsm + rowid * VPAD + lane * 2) = *(const uint2*)(g_v + base);
    }
    __syncthreads();

    // phase 2: score mma — 12 n-tiles, warp w does tile w (w < 12)
    if (warp < 12) {
        uint32_t af[8][4];
#pragma unroll
        for (int ks = 0; ks < 8; ks++) {
            int kb = ks * 8;
            af[ks][0] = qsm[g * LDU + kb + tg];
            af[ks][1] = qsm[(g + 8) * LDU + kb + tg];
            af[ks][2] = qsm[g * LDU + kb + tg + 4];
            af[ks][3] = qsm[(g + 8) * LDU + kb + tg + 4];
        }
        float a4[4] = {0.f, 0.f, 0.f, 0.f};
        int n = warp * 8 + g;
#pragma unroll
        for (int ks = 0; ks < 8; ks++) {
            int kb = ks * 8;
            uint32_t bf[2];
            bf[0] = ksm[n * LDU + kb + tg];
            bf[1] = ksm[n * LDU + kb + tg + 4];
            mma_bf16(a4, af[ks], bf);
        }
        *(float2*)(scall + g * SCW + warp * 8 + 2 * tg) = make_float2(a4[0], a4[1]);
        *(float2*)(scall + (g + 8) * SCW + warp * 8 + 2 * tg) = make_float2(a4[2], a4[3]);
    }
    __syncthreads();

    // phase 3: softmax — warp j, position j
    {
        float s = -1e30f;
        if (lane < 27)
            s = sc[j * 32 + lane] + scall[j * SCW + sl[j * 32 + lane]];
        float m = s;
#pragma unroll
        for (int o = 16; o; o >>= 1) m = fmaxf(m, __shfl_xor_sync(0xffffffffu, m, o));
        float e = (lane < 27) ? __expf(s - m) : 0.f;
        float den = e;
#pragma unroll
        for (int o = 16; o; o >>= 1) den += __shfl_xor_sync(0xffffffffu, den, o);
        aw[j * 32 + lane] = e / den;
    }
    __syncwarp();

    // phase 4: AV — warp j, position j
    {
        float4 acc = {0.f, 0.f, 0.f, 0.f};
#pragma unroll
        for (int n = 0; n < 27; n++) {
            float a = aw[j * 32 + n];
            int slot = sl[j * 32 + n];
            uint2 vv = *(const uint2*)(vsm + slot * VPAD + lane * 2);
            float2 f0 = __bfloat1622float2(*(const __nv_bfloat162*)&vv.x);
            float2 f1 = __bfloat1622float2(*(const __nv_bfloat162*)&vv.y);
            acc.x = fmaf(a, f0.x, acc.x);
            acc.y = fmaf(a, f0.y, acc.y);
            acc.z = fmaf(a, f1.x, acc.z);
            acc.w = fmaf(a, f1.y, acc.w);
        }
        uint2 o = { pack_bf16(acc.x, acc.y), pack_bf16(acc.z, acc.w) };
        *(uint2*)(g_att + p * 64 + lane * 2) = o;
    }
}

static const int ATTN_SMEM =
    (16 * LDU + 96 * LDU + 96 * VPAD + 16 * SCW + 512 * 3 + 96) * 4;  // 68992 B
static_assert((16 * LDU + 96 * LDU + 96 * VPAD + 16 * SCW + 512 * 3 + 96) * 4
              <= 227 * 1024, "attn smem");

// ---------------------------------------------------------------------------
extern "C" void kernel_launch(void* const* d_in, const int* in_sizes, int n_in,
                              void* d_out, int out_size) {
    const float* x      = (const float*)d_in[0];
    const float* gamma  = (const float*)d_in[1];
    const float* qkv_w  = (const float*)d_in[2];
    const float* qkv_b  = (const float*)d_in[3];
    const float* rpb    = (const float*)d_in[4];
    const float* proj_w = (const float*)d_in[5];
    const float* proj_b = (const float*)d_in[6];
    float* out = (float*)d_out;

    cudaFuncSetAttribute(attn_kernel, cudaFuncAttributeMaxDynamicSharedMemorySize, ATTN_SMEM);
    cudaFuncSetAttribute(gemm_qkv,  cudaFuncAttributeMaxDynamicSharedMemorySize, QKV_SMEM);
    cudaFuncSetAttribute(gemm_proj, cudaFuncAttributeMaxDynamicSharedMemorySize, PROJ_SMEM);

    prep_w<<<128, 256>>>(qkv_w, proj_w);
    inv_kernel<<<(NS / 4 + 255) / 256, 256>>>(x);
    gemm_qkv<<<dim3(3, NS / 64), 256, QKV_SMEM>>>(x, gamma, qkv_b);
    attn_kernel<<<dim3(WW / 4, HH / 2, TT / 2), 512, ATTN_SMEM>>>(rpb);
    gemm_proj<<<dim3(2, NS / 64), 128, PROJ_SMEM>>>(proj_b, x, out);
}

// round 15
// speedup vs baseline: 1.2604x; 1.1111x over previous
#include <cuda_runtime.h>
#include <cuda_bf16.h>
#include <math.h>
#include <stdint.h>

#define NS 19200   // T*H*W
#define TT 12
#define HH 40
#define WW 40
#define CC 128

// Scratch (device globals)
__device__ float    g_inv[NS];           // per-position inv-norm * sqrt(C)
__device__ uint32_t g_q[NS * 64];        // q rows, bf16x2, pre-scaled by C^-0.5
__device__ uint32_t g_k[NS * 64];        // k rows, bf16x2
__device__ uint32_t g_v[NS * 64];        // v rows, bf16x2
__device__ uint32_t g_att[NS * 64];      // attention output rows, bf16x2
__device__ uint32_t g_wqkv[384 * 64];    // qkv_w bf16x2
__device__ uint32_t g_wproj[128 * 64];   // proj_w bf16x2

__device__ __forceinline__ void mma_bf16(float* c, const uint32_t* a, const uint32_t* b) {
    asm volatile(
        "mma.sync.aligned.m16n8k16.row.col.f32.bf16.bf16.f32 "
        "{%0,%1,%2,%3}, {%4,%5,%6,%7}, {%8,%9}, {%0,%1,%2,%3};\n"
        : "+f"(c[0]), "+f"(c[1]), "+f"(c[2]), "+f"(c[3])
        : "r"(a[0]), "r"(a[1]), "r"(a[2]), "r"(a[3]), "r"(b[0]), "r"(b[1]));
}

__device__ __forceinline__ uint32_t pack_bf16(float x, float y) {
    uint32_t r;
    asm("cvt.rn.bf16x2.f32 %0, %1, %2;" : "=r"(r) : "f"(y), "f"(x));  // lo=x, hi=y
    return r;
}

__device__ __forceinline__ void cp8(uint32_t dst, const void* src) {
    asm volatile("cp.async.ca.shared.global [%0], [%1], 8;" :: "r"(dst), "l"(src));
}

// ---------------------------------------------------------------------------
// Kernel 0: weight prep, fp32 -> bf16x2
// ---------------------------------------------------------------------------
__global__ void prep_w(const float* __restrict__ qkv_w, const float* __restrict__ proj_w) {
    int i = blockIdx.x * blockDim.x + threadIdx.x;   // 0 .. 32767
    if (i < 384 * 64) {
        float2 v = *(const float2*)(qkv_w + i * 2);
        g_wqkv[i] = pack_bf16(v.x, v.y);
    } else {
        int j = i - 384 * 64;
        float2 v = *(const float2*)(proj_w + j * 2);
        g_wproj[j] = pack_bf16(v.x, v.y);
    }
}

// ---------------------------------------------------------------------------
// Kernel 1: per-position inv norm, one thread per position (75 CTAs, MLP 16)
// ---------------------------------------------------------------------------
__global__ void inv_kernel(const float* __restrict__ x) {
    int s = blockIdx.x * blockDim.x + threadIdx.x;
    if (s >= NS) return;
    float ss = 0.f;
#pragma unroll 16
    for (int c = 0; c < CC; c++) {
        float v = x[(size_t)c * NS + s];
        ss = fmaf(v, v, ss);
    }
    g_inv[s] = 11.313708498984761f / fmaxf(sqrtf(ss), 1e-12f);  // sqrt(128)/||x||
}

// ---------------------------------------------------------------------------
// GEMM common bits
// ---------------------------------------------------------------------------
#define LDU 68
#define A_U (64 * LDU)
#define B128_U (128 * LDU)

__device__ __forceinline__ void gemm_core(const uint32_t* As, const uint32_t* Bs,
                                          int wm, int wn, int g, int tg,
                                          float acc[2][4][4]) {
#pragma unroll
    for (int ks = 0; ks < 8; ks++) {
        int kb = ks * 8;
        uint32_t af[2][4], bf[4][2];
#pragma unroll
        for (int mt = 0; mt < 2; mt++) {
            int m = wm * 32 + mt * 16 + g;
            af[mt][0] = As[m * LDU + kb + tg];
            af[mt][1] = As[(m + 8) * LDU + kb + tg];
            af[mt][2] = As[m * LDU + kb + tg + 4];
            af[mt][3] = As[(m + 8) * LDU + kb + tg + 4];
        }
#pragma unroll
        for (int nt = 0; nt < 4; nt++) {
            int n = wn * 32 + nt * 8 + g;
            bf[nt][0] = Bs[n * LDU + kb + tg];
            bf[nt][1] = Bs[n * LDU + kb + tg + 4];
        }
#pragma unroll
        for (int mt = 0; mt < 2; mt++)
#pragma unroll
            for (int nt = 0; nt < 4; nt++)
                mma_bf16(acc[mt][nt], af[mt], bf[nt]);
    }
}

// ---------------------------------------------------------------------------
// Kernel 2: qkv GEMM (round-10..14 winner, unchanged)
// ---------------------------------------------------------------------------
#define QKV_SMEM ((A_U + B128_U) * 4)   // 52224 B
static_assert(QKV_SMEM <= 227 * 1024, "qkv smem");

__global__ void __launch_bounds__(256, 2)
gemm_qkv(const float* __restrict__ x, const float* __restrict__ gamma,
         const float* __restrict__ bias) {
    extern __shared__ uint32_t su[];
    uint32_t* As = su;
    uint32_t* Bs = su + A_U;

    int tid = threadIdx.x;
    int lane = tid & 31;
    int warp = tid >> 5;
    int wm = warp & 1, wn = warp >> 1;
    int g = lane >> 2, tg = lane & 3;
    int bx = blockIdx.x, by = blockIdx.y;

#pragma unroll
    for (int i = 0; i < 8; i++) {
        int id = tid + i * 256;
        int r = id >> 5, c4 = (id & 31) << 2;
        int row = by * 64 + r;
        int ch = row / 150;
        int s = (row - ch * 150) * 128 + c4;
        float gm = __ldg(&gamma[ch]);
        float4 iv = *(const float4*)(g_inv + s);
        float4 v = *(const float4*)(x + (size_t)row * 128 + c4);
        v.x *= iv.x * gm; v.y *= iv.y * gm; v.z *= iv.z * gm; v.w *= iv.w * gm;
        As[r * LDU + (c4 >> 1)]     = pack_bf16(v.x, v.y);
        As[r * LDU + (c4 >> 1) + 1] = pack_bf16(v.z, v.w);
    }
    const uint32_t* Bbase = g_wqkv + (size_t)bx * 128 * 64;
#pragma unroll
    for (int i = 0; i < 8; i++) {
        int id = tid + i * 256;
        int r = id >> 4, c = (id & 15) * 4;
        uint4 v = *(const uint4*)(Bbase + r * 64 + c);
        *(uint4*)(Bs + r * LDU + c) = v;
    }
    __syncthreads();

    float acc[2][4][4];
#pragma unroll
    for (int i = 0; i < 2; i++)
#pragma unroll
        for (int j = 0; j < 4; j++)
#pragma unroll
            for (int e = 0; e < 4; e++) acc[i][j][e] = 0.f;

    gemm_core(As, Bs, wm, wn, g, tg, acc);

    const float QS = 0.08838834764831845f;
    uint32_t* dst = (bx == 0) ? g_q : (bx == 1) ? g_k : g_v;
    float sc = (bx == 0) ? QS : 1.0f;
#pragma unroll
    for (int nt = 0; nt < 4; nt++) {
        int nloc = wn * 32 + nt * 8 + 2 * tg;
        float2 bb = *(const float2*)(bias + bx * 128 + nloc);
#pragma unroll
        for (int mt = 0; mt < 2; mt++) {
            int row0 = by * 64 + wm * 32 + mt * 16 + g;
            dst[row0 * 64 + (nloc >> 1)] =
                pack_bf16((acc[mt][nt][0] + bb.x) * sc, (acc[mt][nt][1] + bb.y) * sc);
            dst[(row0 + 8) * 64 + (nloc >> 1)] =
                pack_bf16((acc[mt][nt][2] + bb.x) * sc, (acc[mt][nt][3] + bb.y) * sc);
        }
    }
}

// ---------------------------------------------------------------------------
// Kernel 4: proj GEMM (round-10..14 winner, unchanged)
// ---------------------------------------------------------------------------
#define PROJ_SMEM (2 * A_U * 4)   // 34816 B
static_assert(PROJ_SMEM <= 227 * 1024, "proj smem");

__global__ void __launch_bounds__(128, 5)
gemm_proj(const float* __restrict__ bias,
          const float* __restrict__ resid, float* __restrict__ outArg) {
    extern __shared__ uint32_t su[];
    uint32_t* As = su;
    uint32_t* Bs = su + A_U;

    int tid = threadIdx.x;
    int lane = tid & 31;
    int warp = tid >> 5;
    int wm = warp & 1, wn = warp >> 1;
    int g = lane >> 2, tg = lane & 3;

    const uint32_t* Abase = g_att + (size_t)blockIdx.y * 64 * 64;
#pragma unroll
    for (int i = 0; i < 8; i++) {
        int id = tid + i * 128;
        int r = id >> 4, c = (id & 15) * 4;
        uint4 v = *(const uint4*)(Abase + r * 64 + c);
        *(uint4*)(As + r * LDU + c) = v;
    }
    const uint32_t* Bbase = g_wproj + (size_t)blockIdx.x * 64 * 64;
#pragma unroll
    for (int i = 0; i < 8; i++) {
        int id = tid + i * 128;
        int r = id >> 4, c = (id & 15) * 4;
        uint4 v = *(const uint4*)(Bbase + r * 64 + c);
        *(uint4*)(Bs + r * LDU + c) = v;
    }
    __syncthreads();

    float acc[2][4][4];
#pragma unroll
    for (int i = 0; i < 2; i++)
#pragma unroll
        for (int j = 0; j < 4; j++)
#pragma unroll
            for (int e = 0; e < 4; e++) acc[i][j][e] = 0.f;

    gemm_core(As, Bs, wm, wn, g, tg, acc);

#pragma unroll
    for (int nt = 0; nt < 4; nt++) {
        int n = blockIdx.x * 64 + wn * 32 + nt * 8 + 2 * tg;
        float2 bb = *(const float2*)(bias + n);
#pragma unroll
        for (int mt = 0; mt < 2; mt++) {
            int row0 = blockIdx.y * 64 + wm * 32 + mt * 16 + g;
            float2 r0 = *(const float2*)(resid + (size_t)row0 * 128 + n);
            float2 r1 = *(const float2*)(resid + (size_t)(row0 + 8) * 128 + n);
            float2 o0 = { acc[mt][nt][0] + bb.x + r0.x, acc[mt][nt][1] + bb.y + r0.y };
            float2 o1 = { acc[mt][nt][2] + bb.x + r1.x, acc[mt][nt][3] + bb.y + r1.y };
            *(float2*)(outArg + (size_t)row0 * 128 + n) = o0;
            *(float2*)(outArg + (size_t)(row0 + 8) * 128 + n) = o1;
        }
    }
}

// ---------------------------------------------------------------------------
// Kernel 3: neighborhood attention, 16 positions/CTA, 512 threads.
// cp.async staging of K/V/q issued at entry (neighbor addresses computed
// inline per warp) overlaps the sl/sc table build; ONE sync covers both.
// ---------------------------------------------------------------------------
#define VPAD 66    // u32 stride for v rows
#define SCW 104    // scall row stride (floats)

__global__ void __launch_bounds__(512)
attn_kernel(const float* __restrict__ rpb) {
    extern __shared__ uint32_t smu[];
    uint32_t* qsm   = smu;                        // [16][LDU]
    uint32_t* ksm   = qsm + 16 * LDU;             // [96][LDU]
    uint32_t* vsm   = ksm + 96 * LDU;             // [96][VPAD]
    float*    scall = (float*)(vsm + 96 * VPAD);  // [16][SCW]
    float*    sc    = scall + 16 * SCW;           // [16][32] bias
    float*    aw    = sc + 512;                   // [16][32] weights
    int*      sl    = (int*)(aw + 512);           // [16][32] slots

    int tid = threadIdx.x, lane = tid & 31, warp = tid >> 5;   // warp 0..15
    int g = lane >> 2, tg = lane & 3;
    int w0 = blockIdx.x * 4, h0 = blockIdx.y * 2, t0 = blockIdx.z * 2;

    int tlo = min(max(t0 - 1, 0), TT - 3);
    int hlo = min(max(h0 - 1, 0), HH - 3);
    int wlo = min(max(w0 - 1, 0), WW - 3);

    // warp j -> position j
    int j = warp;
    int pt = t0 + (j >> 3), ph = h0 + ((j >> 2) & 1), pw = w0 + (j & 3);
    int p  = (pt * HH + ph) * WW + pw;

    // phase 0a: issue cp.async staging (6 k/v rows + 1 q row per warp)
    uint32_t qs_b = (uint32_t)__cvta_generic_to_shared(qsm);
    uint32_t ks_b = (uint32_t)__cvta_generic_to_shared(ksm);
    uint32_t vs_b = (uint32_t)__cvta_generic_to_shared(vsm);
    cp8(qs_b + (j * LDU + lane * 2) * 4, g_q + p * 64 + lane * 2);
#pragma unroll
    for (int i = 0; i < 6; i++) {
        int rowid = warp + i * 16;
        int dt = rowid / 24, rrem = rowid % 24;
        int dh = rrem / 6, dw = rrem % 6;
        int nt = min(tlo + dt, TT - 1);
        int nh = min(hlo + dh, HH - 1);
        int nw = min(wlo + dw, WW - 1);
        int base = ((nt * HH + nh) * WW + nw) * 64 + lane * 2;
        cp8(ks_b + (rowid * LDU + lane * 2) * 4, g_k + base);
        cp8(vs_b + (rowid * VPAD + lane * 2) * 4, g_v + base);
    }
    asm volatile("cp.async.commit_group;");

    // phase 0b: sl/sc tables (432 <= 512, single pass) while staging flies
    if (tid < 432) {
        int jj = tid / 27, n = tid % 27;
        int qt = t0 + (jj >> 3), qh = h0 + ((jj >> 2) & 1), qw = w0 + (jj & 3);
        int dt = n / 9, dh = (n / 3) % 3, dw = n % 3;
        int stt = min(max(qt - 1, 0), TT - 3);
        int sh  = min(max(qh - 1, 0), HH - 3);
        int sw  = min(max(qw - 1, 0), WW - 3);
        int nt = stt + dt, nh = sh + dh, nw = sw + dw;
        sl[jj * 32 + n] = ((nt - tlo) * 4 + (nh - hlo)) * 6 + (nw - wlo);
        int bt = nt - qt + 2, bh = nh - qh + 2, bw = nw - qw + 2;
        sc[jj * 32 + n] = __ldg(&rpb[(bt * 5 + bh) * 5 + bw]);
    }
    asm volatile("cp.async.wait_group 0;");
    __syncthreads();

    // phase 1: score mma — 12 n-tiles, warp w does tile w (w < 12)
    if (warp < 12) {
        uint32_t af[8][4];
#pragma unroll
        for (int ks = 0; ks < 8; ks++) {
            int kb = ks * 8;
            af[ks][0] = qsm[g * LDU + kb + tg];
            af[ks][1] = qsm[(g + 8) * LDU + kb + tg];
            af[ks][2] = qsm[g * LDU + kb + tg + 4];
            af[ks][3] = qsm[(g + 8) * LDU + kb + tg + 4];
        }
        float a4[4] = {0.f, 0.f, 0.f, 0.f};
        int n = warp * 8 + g;
#pragma unroll
        for (int ks = 0; ks < 8; ks++) {
            int kb = ks * 8;
            uint32_t bf[2];
            bf[0] = ksm[n * LDU + kb + tg];
            bf[1] = ksm[n * LDU + kb + tg + 4];
            mma_bf16(a4, af[ks], bf);
        }
        *(float2*)(scall + g * SCW + warp * 8 + 2 * tg) = make_float2(a4[0], a4[1]);
        *(float2*)(scall + (g + 8) * SCW + warp * 8 + 2 * tg) = make_float2(a4[2], a4[3]);
    }
    __syncthreads();

    // phase 2: softmax — warp j, position j
    {
        float s = -1e30f;
        if (lane < 27)
            s = sc[j * 32 + lane] + scall[j * SCW + sl[j * 32 + lane]];
        float m = s;
#pragma unroll
        for (int o = 16; o; o >>= 1) m = fmaxf(m, __shfl_xor_sync(0xffffffffu, m, o));
        float e = (lane < 27) ? __expf(s - m) : 0.f;
        float den = e;
#pragma unroll
        for (int o = 16; o; o >>= 1) den += __shfl_xor_sync(0xffffffffu, den, o);
        aw[j * 32 + lane] = e / den;
    }
    __syncwarp();

    // phase 3: AV — warp j, position j
    {
        float4 acc = {0.f, 0.f, 0.f, 0.f};
#pragma unroll
        for (int n = 0; n < 27; n++) {
            float a = aw[j * 32 + n];
            int slot = sl[j * 32 + n];
            uint2 vv = *(const uint2*)(vsm + slot * VPAD + lane * 2);
            float2 f0 = __bfloat1622float2(*(const __nv_bfloat162*)&vv.x);
            float2 f1 = __bfloat1622float2(*(const __nv_bfloat162*)&vv.y);
            acc.x = fmaf(a, f0.x, acc.x);
            acc.y = fmaf(a, f0.y, acc.y);
            acc.z = fmaf(a, f1.x, acc.z);
            acc.w = fmaf(a, f1.y, acc.w);
        }
        uint2 o = { pack_bf16(acc.x, acc.y), pack_bf16(acc.z, acc.w) };
        *(uint2*)(g_att + p * 64 + lane * 2) = o;
    }
}

static const int ATTN_SMEM =
    (16 * LDU + 96 * LDU + 96 * VPAD + 16 * SCW + 512 * 3) * 4;  // 68608 B
static_assert((16 * LDU + 96 * LDU + 96 * VPAD + 16 * SCW + 512 * 3) * 4
              <= 227 * 1024, "attn smem");

// ---------------------------------------------------------------------------
extern "C" void kernel_launch(void* const* d_in, const int* in_sizes, int n_in,
                              void* d_out, int out_size) {
    const float* x      = (const float*)d_in[0];
    const float* gamma  = (const float*)d_in[1];
    const float* qkv_w  = (const float*)d_in[2];
    const float* qkv_b  = (const float*)d_in[3];
    const float* rpb    = (const float*)d_in[4];
    const float* proj_w = (const float*)d_in[5];
    const float* proj_b = (const float*)d_in[6];
    float* out = (float*)d_out;

    cudaFuncSetAttribute(attn_kernel, cudaFuncAttributeMaxDynamicSharedMemorySize, ATTN_SMEM);
    cudaFuncSetAttribute(gemm_qkv,  cudaFuncAttributeMaxDynamicSharedMemorySize, QKV_SMEM);
    cudaFuncSetAttribute(gemm_proj, cudaFuncAttributeMaxDynamicSharedMemorySize, PROJ_SMEM);

    prep_w<<<128, 256>>>(qkv_w, proj_w);
    inv_kernel<<<(NS + 255) / 256, 256>>>(x);
    gemm_qkv<<<dim3(3, NS / 64), 256, QKV_SMEM>>>(x, gamma, qkv_b);
    attn_kernel<<<dim3(WW / 4, HH / 2, TT / 2), 512, ATTN_SMEM>>>(rpb);
    gemm_proj<<<dim3(2, NS / 64), 128, PROJ_SMEM>>>(proj_b, x, out);
}